// round 1
// baseline (speedup 1.0000x reference)
#include <cuda_runtime.h>
#include <cstdint>
#include <cstddef>

// Problem dims (fixed for this problem instance)
#define TT     4
#define BATCH  8
#define NTOK   1024
#define CDIM   768
#define HDIM   3072
#define NHEAD  8
#define DHEAD  96
#define WIN    8
#define NWIN   128
#define BNALL  (BATCH*NTOK)          // 8192 (b,n) rows; full M = TT*BNALL = 32768

// ---------------------------------------------------------------------------
// Scratch (static device globals — allocation-free per harness rules)
// ---------------------------------------------------------------------------
__device__ __align__(16) unsigned char g_qkv[(size_t)TT*BATCH*NTOK*3*CDIM]; // 75.5 MB spikes {0,1}
__device__ __align__(16) unsigned char g_osp[(size_t)TT*BATCH*NTOK*CDIM];   // 25.2 MB attn spikes
__device__ __align__(16) float         g_x1 [(size_t)TT*BATCH*NTOK*CDIM];   // 100.7 MB  x + proj
__device__ __align__(16) unsigned char g_h  [(size_t)TT*BATCH*NTOK*HDIM];   // 100.7 MB  f1 spikes

// ---------------------------------------------------------------------------
// f32x2 packed-FMA helpers (Blackwell: FFMA-3reg is rt=2/SMSP; f32x2 doubles it)
// Bitwise identical per-lane to scalar fp32 FMA.
// ---------------------------------------------------------------------------
__device__ __forceinline__ unsigned long long pack2(float x){
    unsigned long long r;
    asm("mov.b64 %0, {%1, %1};" : "=l"(r) : "f"(x));
    return r;
}
__device__ __forceinline__ void fma2(unsigned long long &d,
                                     unsigned long long a, unsigned long long b){
    asm("fma.rn.f32x2 %0, %1, %2, %0;" : "+l"(d) : "l"(a), "l"(b));
}
__device__ __forceinline__ float2 unpack2(unsigned long long v){
    float2 r;
    asm("mov.b64 {%0, %1}, %2;" : "=f"(r.x), "=f"(r.y) : "l"(v));
    return r;
}

// ---------------------------------------------------------------------------
// Fused GEMM + BN-affine + LIF kernel.
//   A: [TT*BNALL, K]  (float or u8 spikes),  row index = t*BNALL + bn
//   W: [OCdim, K] row-major  (y[.,o] = sum_c A[.,c]*W[o,c])
//   y = (acc + Bb[o]) * Sc[o] + Sh[o]; LIF over t (tau=2, hard reset, vth)
//   ADD_RES=false : write spike (u8) to Outp[(t*BNALL+bn)*OCtot + ocBase + oc]
//   ADD_RES=true  : write Res[idx] + spike (float) to Outp[idx]
// Tile: 32 bn x 128 oc x 4 t per block, 256 threads, KT=16.
// Per-thread: 2 bn x 8 oc x 4 t, accumulators packed f32x2 over oc pairs.
// ---------------------------------------------------------------------------
template<bool AU8, bool ADD_RES>
__global__ __launch_bounds__(256, 2)
void gemm_lif_kernel(const void* __restrict__ Ap,
                     const float* __restrict__ W,
                     const float* __restrict__ Bb,
                     const float* __restrict__ Sc,
                     const float* __restrict__ Sh,
                     void* __restrict__ Outp,
                     const float* __restrict__ Res,
                     int K, int OCtot, int ocBase, float vth)
{
    const int tid = threadIdx.x;
    const int ocT = tid & 15;        // 16 threads over oc, 8 each
    const int bnT = tid >> 4;        // 16 threads over bn, 2 each
    const int bn0 = blockIdx.y * 32;
    const int oc0 = blockIdx.x * 128;

    __shared__ float As[16][4][34];  // [k][t][bn] (+pad)
    __shared__ float Bs[16][128];    // [k][oc]

    unsigned long long acc[4][2][4]; // [t][bn_i][oc_pair]
    #pragma unroll
    for (int t=0;t<4;t++)
        #pragma unroll
        for (int i=0;i<2;i++)
            #pragma unroll
            for (int j=0;j<4;j++) acc[t][i][j] = 0ull;

    const int nk = K >> 4;

    float4 aP[2]; uint4 uP; float4 bP[2];

    auto loadTile = [&](int kt){
        const int k0 = kt * 16;
        if constexpr (AU8){
            if (tid < 128){
                const int t = tid >> 5, bn = tid & 31;
                uP = *reinterpret_cast<const uint4*>(
                    (const unsigned char*)Ap + (size_t)(t*BNALL + bn0 + bn)*K + k0);
            }
        } else {
            #pragma unroll
            for (int r=0;r<2;r++){
                const int v = tid*2 + r;
                const int t = v >> 7, bn = (v >> 2) & 31, kv = v & 3;
                aP[r] = *reinterpret_cast<const float4*>(
                    (const float*)Ap + (size_t)(t*BNALL + bn0 + bn)*K + k0 + kv*4);
            }
        }
        #pragma unroll
        for (int r=0;r<2;r++){
            const int v = tid*2 + r;
            const int oc = v >> 2, kv = v & 3;
            bP[r] = *reinterpret_cast<const float4*>(
                W + (size_t)(oc0 + oc)*K + k0 + kv*4);
        }
    };

    auto storeTile = [&](){
        if constexpr (AU8){
            if (tid < 128){
                const int t = tid >> 5, bn = tid & 31;
                unsigned int wv[4] = {uP.x, uP.y, uP.z, uP.w};
                #pragma unroll
                for (int k=0;k<16;k++)
                    As[k][t][bn] = (float)((wv[k>>2] >> ((k&3)*8)) & 255u);
            }
        } else {
            #pragma unroll
            for (int r=0;r<2;r++){
                const int v = tid*2 + r;
                const int t = v >> 7, bn = (v >> 2) & 31, kv = v & 3;
                As[kv*4+0][t][bn] = aP[r].x;
                As[kv*4+1][t][bn] = aP[r].y;
                As[kv*4+2][t][bn] = aP[r].z;
                As[kv*4+3][t][bn] = aP[r].w;
            }
        }
        #pragma unroll
        for (int r=0;r<2;r++){
            const int v = tid*2 + r;
            const int oc = v >> 2, kv = v & 3;
            Bs[kv*4+0][oc] = bP[r].x;
            Bs[kv*4+1][oc] = bP[r].y;
            Bs[kv*4+2][oc] = bP[r].z;
            Bs[kv*4+3][oc] = bP[r].w;
        }
    };

    loadTile(0);
    for (int kt = 0; kt < nk; kt++){
        storeTile();
        __syncthreads();
        if (kt + 1 < nk) loadTile(kt + 1);
        #pragma unroll
        for (int k=0;k<16;k++){
            unsigned long long b2[4];
            #pragma unroll
            for (int j=0;j<4;j++)
                b2[j] = *reinterpret_cast<const unsigned long long*>(&Bs[k][ocT*8 + j*2]);
            #pragma unroll
            for (int t=0;t<4;t++){
                const float2 av = *reinterpret_cast<const float2*>(&As[k][t][bnT*2]);
                const unsigned long long a0 = pack2(av.x);
                const unsigned long long a1 = pack2(av.y);
                #pragma unroll
                for (int j=0;j<4;j++){
                    fma2(acc[t][0][j], a0, b2[j]);
                    fma2(acc[t][1][j], a1, b2[j]);
                }
            }
        }
        __syncthreads();
    }

    // Epilogue: BN affine + LIF over t, then store
    #pragma unroll
    for (int i=0;i<2;i++){
        const int bng = bn0 + bnT*2 + i;
        #pragma unroll
        for (int j2=0;j2<4;j2++){
            const int ocA = oc0 + ocT*8 + j2*2;
            const float b0 = Bb[ocA],   b1 = Bb[ocA+1];
            const float s0 = Sc[ocA],   s1 = Sc[ocA+1];
            const float h0 = Sh[ocA],   h1 = Sh[ocA+1];
            float v0 = 0.f, v1 = 0.f;
            #pragma unroll
            for (int t=0;t<4;t++){
                const float2 y = unpack2(acc[t][i][j2]);
                float y0 = (y.x + b0) * s0 + h0;
                float y1 = (y.y + b1) * s1 + h1;
                v0 += (y0 - v0) * 0.5f;
                v1 += (y1 - v1) * 0.5f;
                const float sp0 = (v0 >= vth) ? 1.f : 0.f;
                const float sp1 = (v1 >= vth) ? 1.f : 0.f;
                const size_t idx = (size_t)(t*BNALL + bng)*OCtot + ocBase + ocA;
                if constexpr (ADD_RES){
                    ((float*)Outp)[idx]     = Res[idx]     + sp0;
                    ((float*)Outp)[idx + 1] = Res[idx + 1] + sp1;
                } else {
                    ((unsigned char*)Outp)[idx]     = (unsigned char)sp0;
                    ((unsigned char*)Outp)[idx + 1] = (unsigned char)sp1;
                }
                v0 *= (1.f - sp0);
                v1 *= (1.f - sp1);
            }
        }
    }
}

// ---------------------------------------------------------------------------
// Local attention on binary spikes + fused attn_lif (vth=0.5) over T.
// One block per (b, h, window). Windows of 8 queries attend to 16 keys
// (previous window + own window); first window masked to own 8.
// ---------------------------------------------------------------------------
__global__ __launch_bounds__(128)
void attn_kernel(const unsigned char* __restrict__ qkv,
                 unsigned char* __restrict__ osp)
{
    const int blk = blockIdx.x;
    const int nw = blk & (NWIN-1);
    const int h  = (blk >> 7) & (NHEAD-1);
    const int bb = blk >> 10;
    const int n0 = nw * WIN;
    const int tid = threadIdx.x;

    __shared__ float qs[8][96];
    __shared__ float ks[16][100];
    __shared__ float vs[16][100];
    __shared__ float p_sh[8][16];
    __shared__ float vst[768];

    for (int idx = tid; idx < 768; idx += 128) vst[idx] = 0.f;

    const int i_ = tid >> 4;   // query row 0..7
    const int j_ = tid & 15;   // key col 0..15
    const float SCALE = 0.10206207261596577f;  // 96^-0.5

    for (int t = 0; t < TT; t++){
        const int rowbase = (t*BATCH + bb) * NTOK;
        // load q window
        for (int idx = tid; idx < 8*96; idx += 128){
            const int i = idx / 96, d = idx - 96*i;
            qs[i][d] = (float)qkv[(size_t)(rowbase + n0 + i)*(3*CDIM) + h*DHEAD + d];
        }
        // load k, v windows (16 rows: prev 8 + own 8)
        for (int idx = tid; idx < 16*96; idx += 128){
            const int j = idx / 96, d = idx - 96*j;
            const int n = n0 - 8 + j;
            float kv = 0.f, vv = 0.f;
            if (n >= 0){
                const size_t base = (size_t)(rowbase + n)*(3*CDIM) + h*DHEAD + d;
                kv = (float)qkv[base + CDIM];
                vv = (float)qkv[base + 2*CDIM];
            }
            ks[j][d] = kv;
            vs[j][d] = vv;
        }
        __syncthreads();

        // sim[i][j] = scale * <q_i, k_j>  (dot of binaries = exact count)
        float cnt = 0.f;
        {
            const float4* q4 = reinterpret_cast<const float4*>(&qs[i_][0]);
            const float4* k4 = reinterpret_cast<const float4*>(&ks[j_][0]);
            #pragma unroll
            for (int c = 0; c < 24; c++){
                const float4 a = q4[c], b = k4[c];
                cnt += a.x*b.x + a.y*b.y + a.z*b.z + a.w*b.w;
            }
        }
        float sim = cnt * SCALE;
        if (nw == 0 && j_ < 8) sim = -3.402823466e+38f;   // mask lookback of first window

        // softmax over j within 16-lane groups
        float mx = sim;
        #pragma unroll
        for (int o = 8; o; o >>= 1) mx = fmaxf(mx, __shfl_xor_sync(0xffffffffu, mx, o));
        const float e = expf(sim - mx);
        float sm = e;
        #pragma unroll
        for (int o = 8; o; o >>= 1) sm += __shfl_xor_sync(0xffffffffu, sm, o);
        p_sh[i_][j_] = e / sm;
        __syncthreads();

        // out[i][d] = sum_j p[i][j] * v[j][d]; fused attn_lif (vth=0.5)
        for (int idx = tid; idx < 8*96; idx += 128){
            const int i = idx / 96, d = idx - 96*i;
            float o = 0.f;
            #pragma unroll
            for (int j = 0; j < 16; j++) o += p_sh[i][j] * vs[j][d];
            float v = vst[idx];
            v += (o - v) * 0.5f;
            const float sp = (v >= 0.5f) ? 1.f : 0.f;
            osp[(size_t)(rowbase + n0 + i)*CDIM + h*DHEAD + d] = (unsigned char)sp;
            vst[idx] = v * (1.f - sp);
        }
        __syncthreads();
    }
}

// ---------------------------------------------------------------------------
// Launch
// ---------------------------------------------------------------------------
extern "C" void kernel_launch(void* const* d_in, const int* in_sizes, int n_in,
                              void* d_out, int out_size)
{
    const float* x   = (const float*)d_in[0];
    const float* qw  = (const float*)d_in[1];
    const float* qb  = (const float*)d_in[2];
    const float* qs_ = (const float*)d_in[3];
    const float* qt  = (const float*)d_in[4];
    const float* kw  = (const float*)d_in[5];
    const float* kb  = (const float*)d_in[6];
    const float* ks_ = (const float*)d_in[7];
    const float* kt  = (const float*)d_in[8];
    const float* vw  = (const float*)d_in[9];
    const float* vb  = (const float*)d_in[10];
    const float* vs_ = (const float*)d_in[11];
    const float* vt  = (const float*)d_in[12];
    const float* pw  = (const float*)d_in[13];
    const float* pb  = (const float*)d_in[14];
    const float* ps  = (const float*)d_in[15];
    const float* pt  = (const float*)d_in[16];
    const float* f1w = (const float*)d_in[17];
    const float* f1b = (const float*)d_in[18];
    const float* f1s = (const float*)d_in[19];
    const float* f1t = (const float*)d_in[20];
    const float* f2w = (const float*)d_in[21];
    const float* f2b = (const float*)d_in[22];
    const float* f2s = (const float*)d_in[23];
    const float* f2t = (const float*)d_in[24];

    void *p_qkv, *p_osp, *p_x1, *p_h;
    cudaGetSymbolAddress(&p_qkv, g_qkv);
    cudaGetSymbolAddress(&p_osp, g_osp);
    cudaGetSymbolAddress(&p_x1,  g_x1);
    cudaGetSymbolAddress(&p_h,   g_h);

    const dim3 gC(CDIM/128, BNALL/32);   // (6, 256)
    const dim3 gH(HDIM/128, BNALL/32);   // (24, 256)

    // Q / K / V projections -> spikes into g_qkv (concat cols: q|k|v)
    gemm_lif_kernel<false,false><<<gC, 256>>>(x, qw, qb, qs_, qt, p_qkv, nullptr,
                                              CDIM, 3*CDIM, 0,       1.0f);
    gemm_lif_kernel<false,false><<<gC, 256>>>(x, kw, kb, ks_, kt, p_qkv, nullptr,
                                              CDIM, 3*CDIM, CDIM,    1.0f);
    gemm_lif_kernel<false,false><<<gC, 256>>>(x, vw, vb, vs_, vt, p_qkv, nullptr,
                                              CDIM, 3*CDIM, 2*CDIM,  1.0f);

    // Local attention + attn_lif -> spike u8
    attn_kernel<<<BATCH*NHEAD*NWIN, 128>>>((const unsigned char*)p_qkv,
                                           (unsigned char*)p_osp);

    // proj: spikes -> LIF spike, fused residual: x1 = x + spike
    gemm_lif_kernel<true,true><<<gC, 256>>>(p_osp, pw, pb, ps, pt, p_x1, x,
                                            CDIM, CDIM, 0, 1.0f);

    // f1: x1 -> h spikes (u8)
    gemm_lif_kernel<false,false><<<gH, 256>>>(p_x1, f1w, f1b, f1s, f1t, p_h, nullptr,
                                              CDIM, HDIM, 0, 1.0f);

    // f2: h spikes -> LIF spike, fused residual: out = x1 + spike
    gemm_lif_kernel<true,true><<<gC, 256>>>(p_h, f2w, f2b, f2s, f2t, d_out,
                                            (const float*)p_x1,
                                            HDIM, CDIM, 0, 1.0f);
}